// round 3
// baseline (speedup 1.0000x reference)
#include <cuda_runtime.h>
#include <cuda_bf16.h>
#include <math.h>
#include <stdint.h>

#define B_  4
#define T_  2048
#define D_  1024
#define H_  16
#define DH_ 64
#define M_  (B_*T_)      // 8192 rows
#define MAXREL 128

// ---------------- scratch (device globals; no allocs allowed) ----------------
__device__ float g_xn[M_*D_];
__device__ float g_q [M_*D_];
__device__ float g_k [M_*D_];
__device__ float g_v [M_*D_];
__device__ float g_y [M_*D_];

// ---------------- LayerNorm: one block per row ----------------
__global__ void ln_kernel(const float* __restrict__ x, const float* __restrict__ gamma,
                          const float* __restrict__ beta, float* __restrict__ out)
{
    const int row = blockIdx.x;
    const int tid = threadIdx.x;              // 256 threads, 4 floats each
    const float4 v = *(const float4*)(x + (size_t)row*D_ + tid*4);
    float s  = v.x + v.y + v.z + v.w;
    float ss = v.x*v.x + v.y*v.y + v.z*v.z + v.w*v.w;
    #pragma unroll
    for (int off = 16; off; off >>= 1) {
        s  += __shfl_xor_sync(0xffffffffu, s,  off);
        ss += __shfl_xor_sync(0xffffffffu, ss, off);
    }
    __shared__ float sh_s[8], sh_ss[8];
    const int w = tid >> 5;
    if ((tid & 31) == 0) { sh_s[w] = s; sh_ss[w] = ss; }
    __syncthreads();
    float ts = 0.f, tss = 0.f;
    #pragma unroll
    for (int i = 0; i < 8; i++) { ts += sh_s[i]; tss += sh_ss[i]; }
    const float mu   = ts * (1.0f / D_);
    const float var  = tss * (1.0f / D_) - mu * mu;
    const float rstd = rsqrtf(var + 1e-5f);
    const float4 gv = *(const float4*)(gamma + tid*4);
    const float4 bv = *(const float4*)(beta  + tid*4);
    float4 o;
    o.x = (v.x - mu) * rstd * gv.x + bv.x;
    o.y = (v.y - mu) * rstd * gv.y + bv.y;
    o.z = (v.z - mu) * rstd * gv.z + bv.z;
    o.w = (v.w - mu) * rstd * gv.w + bv.w;
    *(float4*)(out + (size_t)row*D_ + tid*4) = o;
}

// ---------------- Tensor-core GEMM (split-bf16, 3-pass) ----------------------
// C[m][n] = scale * sum_k A[m][k]*W[n][k]  (+ res[m][n] if RES)
// CTA tile 128x128, BK=32, 256 threads = 8 warps, warp tile 32x64.
// a = a_hi + a_lo (bf16 each); acc += hi*hi + lo*hi + hi*lo  (fp32 accum).

__device__ __forceinline__ void mma16816(float* d, const uint32_t* a, const uint32_t* b)
{
    asm volatile(
        "mma.sync.aligned.m16n8k16.row.col.f32.bf16.bf16.f32 "
        "{%0,%1,%2,%3}, {%4,%5,%6,%7}, {%8,%9}, {%0,%1,%2,%3};\n"
        : "+f"(d[0]), "+f"(d[1]), "+f"(d[2]), "+f"(d[3])
        : "r"(a[0]), "r"(a[1]), "r"(a[2]), "r"(a[3]), "r"(b[0]), "r"(b[1]));
}

__device__ __forceinline__ uint32_t pack_bf16(__nv_bfloat16 lo, __nv_bfloat16 hi)
{
    __nv_bfloat162 p = __halves2bfloat162(lo, hi);   // lo -> low 16 bits
    return *reinterpret_cast<uint32_t*>(&p);
}

template<bool RES>
__device__ __forceinline__ void mma_gemm_body(
    const float* __restrict__ A, const float* __restrict__ W,
    float* __restrict__ C, const float* __restrict__ res, float scale)
{
    // smem: packed bf16 pairs, row stride 20 words (40 bf16) -> conflict-free frags
    __shared__ uint32_t sAh[128][20], sAl[128][20], sBh[128][20], sBl[128][20];

    const int tid  = threadIdx.x;
    const int warp = tid >> 5, lane = tid & 31;
    const int wm = warp >> 1, wn = warp & 1;        // 4x2 warp grid
    const int g  = lane >> 2, t = lane & 3;
    const int m0 = blockIdx.y * 128, n0 = blockIdx.x * 128;

    float acc[2][8][4];
    #pragma unroll
    for (int i = 0; i < 2; i++)
        #pragma unroll
        for (int j = 0; j < 8; j++)
            #pragma unroll
            for (int c = 0; c < 4; c++) acc[i][j][c] = 0.f;

    const int lrow = tid >> 3;          // 0..31
    const int lcol = (tid & 7) * 4;     // 0..28 step 4 (fp32 col)
    const int lw   = (tid & 7) * 2;     // smem word col

    float4 pa[4], pb[4];

    auto LOADG = [&](int k0) {
        #pragma unroll
        for (int it = 0; it < 4; it++) {
            const int row = lrow + it * 32;
            pa[it] = *(const float4*)(A + (size_t)(m0 + row) * D_ + k0 + lcol);
            pb[it] = *(const float4*)(W + (size_t)(n0 + row) * D_ + k0 + lcol);
        }
    };

    auto STORES = [&]() {
        #pragma unroll
        for (int it = 0; it < 4; it++) {
            const int row = lrow + it * 32;
            const float av[4] = {pa[it].x, pa[it].y, pa[it].z, pa[it].w};
            const float bv[4] = {pb[it].x, pb[it].y, pb[it].z, pb[it].w};
            __nv_bfloat16 ah[4], al[4], bh[4], bl[4];
            #pragma unroll
            for (int e = 0; e < 4; e++) {
                ah[e] = __float2bfloat16_rn(av[e]);
                al[e] = __float2bfloat16_rn(av[e] - __bfloat162float(ah[e]));
                bh[e] = __float2bfloat16_rn(bv[e]);
                bl[e] = __float2bfloat16_rn(bv[e] - __bfloat162float(bh[e]));
            }
            sAh[row][lw]   = pack_bf16(ah[0], ah[1]);
            sAh[row][lw+1] = pack_bf16(ah[2], ah[3]);
            sAl[row][lw]   = pack_bf16(al[0], al[1]);
            sAl[row][lw+1] = pack_bf16(al[2], al[3]);
            sBh[row][lw]   = pack_bf16(bh[0], bh[1]);
            sBh[row][lw+1] = pack_bf16(bh[2], bh[3]);
            sBl[row][lw]   = pack_bf16(bl[0], bl[1]);
            sBl[row][lw+1] = pack_bf16(bl[2], bl[3]);
        }
    };

    LOADG(0);
    for (int k0 = 0; k0 < D_; k0 += 32) {
        __syncthreads();
        STORES();
        __syncthreads();
        if (k0 + 32 < D_) LOADG(k0 + 32);

        #pragma unroll
        for (int ks = 0; ks < 2; ks++) {
            const int w0 = ks * 8 + t;
            uint32_t ah[2][4], al[2][4];
            #pragma unroll
            for (int i = 0; i < 2; i++) {
                const int r = wm * 32 + i * 16 + g;
                ah[i][0] = sAh[r  ][w0];   ah[i][1] = sAh[r+8][w0];
                ah[i][2] = sAh[r  ][w0+4]; ah[i][3] = sAh[r+8][w0+4];
                al[i][0] = sAl[r  ][w0];   al[i][1] = sAl[r+8][w0];
                al[i][2] = sAl[r  ][w0+4]; al[i][3] = sAl[r+8][w0+4];
            }
            #pragma unroll
            for (int j = 0; j < 8; j++) {
                const int n = wn * 64 + j * 8 + g;
                const uint32_t bhf[2] = {sBh[n][w0], sBh[n][w0+4]};
                const uint32_t blf[2] = {sBl[n][w0], sBl[n][w0+4]};
                #pragma unroll
                for (int i = 0; i < 2; i++) {
                    mma16816(acc[i][j], ah[i], bhf);
                    mma16816(acc[i][j], al[i], bhf);
                    mma16816(acc[i][j], ah[i], blf);
                }
            }
        }
    }

    // epilogue
    #pragma unroll
    for (int i = 0; i < 2; i++) {
        const int r0 = m0 + wm * 32 + i * 16 + g;
        #pragma unroll
        for (int j = 0; j < 8; j++) {
            const int c = n0 + wn * 64 + j * 8 + 2 * t;
            float2 v0 = make_float2(acc[i][j][0] * scale, acc[i][j][1] * scale);
            float2 v1 = make_float2(acc[i][j][2] * scale, acc[i][j][3] * scale);
            if (RES) {
                const float2 r0v = *(const float2*)(res + (size_t)r0 * D_ + c);
                const float2 r1v = *(const float2*)(res + (size_t)(r0+8) * D_ + c);
                v0.x += r0v.x; v0.y += r0v.y;
                v1.x += r1v.x; v1.y += r1v.y;
            }
            *(float2*)(C + (size_t)r0     * D_ + c) = v0;
            *(float2*)(C + (size_t)(r0+8) * D_ + c) = v1;
        }
    }
}

// QKV fused (blockIdx.z selects W); q scaled by 1/sqrt(DH)=0.125
__global__ void qkv_kernel(const float* __restrict__ xn,
                           const float* __restrict__ Wq, const float* __restrict__ Wk,
                           const float* __restrict__ Wv,
                           float* __restrict__ q, float* __restrict__ k, float* __restrict__ v)
{
    const float* W; float* C; float scale;
    if (blockIdx.z == 0)      { W = Wq; C = q; scale = 0.125f; }
    else if (blockIdx.z == 1) { W = Wk; C = k; scale = 1.0f; }
    else                      { W = Wv; C = v; scale = 1.0f; }
    mma_gemm_body<false>(xn, W, C, nullptr, scale);
}

__global__ void out_kernel(const float* __restrict__ y, const float* __restrict__ Wo,
                           const float* __restrict__ x, float* __restrict__ out)
{
    mma_gemm_body<true>(y, Wo, out, x, 1.0f);
}

// ---------------- Flash attention with causal mask + relative bias -----------
// Grid: (32 qblocks, 16 heads, 4 batch), 256 threads.
#define SROW 68   // padded row stride
__global__ void attn_kernel(const float* __restrict__ q, const float* __restrict__ k,
                            const float* __restrict__ v, const float* __restrict__ rel,
                            float* __restrict__ y)
{
    extern __shared__ float sm[];
    float* Qst   = sm;                  // [d][i] 64xSROW
    float* Kst   = sm + 64*SROW;        // [d][j]
    float* Pst   = sm + 2*64*SROW;      // [j][i]
    float* Vs    = sm + 3*64*SROW;      // [j][d]
    float* rel_s = sm + 4*64*SROW;      // 129

    const int qb = 31 - (int)blockIdx.x;   // heavy blocks first
    const int h  = blockIdx.y;
    const int b  = blockIdx.z;
    const int tid = threadIdx.x;
    const int tx = tid & 15, ty = tid >> 4;

    for (int i = tid; i <= MAXREL; i += 256) rel_s[i] = rel[h*(MAXREL+1) + i];

    const int qrow0 = b*T_ + qb*64;
    #pragma unroll
    for (int it = 0; it < 4; it++) {
        const int f4 = tid + it*256;
        const int r  = f4 >> 4;
        const int dq = (f4 & 15) * 4;
        const float4 val = *(const float4*)(q + (size_t)(qrow0 + r)*D_ + h*DH_ + dq);
        Qst[(dq+0)*SROW + r] = val.x;
        Qst[(dq+1)*SROW + r] = val.y;
        Qst[(dq+2)*SROW + r] = val.z;
        Qst[(dq+3)*SROW + r] = val.w;
    }

    float mreg[4], lreg[4], o[4][4];
    #pragma unroll
    for (int r = 0; r < 4; r++) {
        mreg[r] = -1e30f; lreg[r] = 0.f;
        #pragma unroll
        for (int c = 0; c < 4; c++) o[r][c] = 0.f;
    }

    for (int kb = 0; kb <= qb; kb++) {
        __syncthreads();
        const int krow0 = b*T_ + kb*64;
        #pragma unroll
        for (int it = 0; it < 4; it++) {
            const int f4 = tid + it*256;
            const int r  = f4 >> 4;
            const int dq = (f4 & 15) * 4;
            const float4 kv = *(const float4*)(k + (size_t)(krow0 + r)*D_ + h*DH_ + dq);
            Kst[(dq+0)*SROW + r] = kv.x;
            Kst[(dq+1)*SROW + r] = kv.y;
            Kst[(dq+2)*SROW + r] = kv.z;
            Kst[(dq+3)*SROW + r] = kv.w;
            *(float4*)(Vs + (size_t)r*SROW + dq) =
                *(const float4*)(v + (size_t)(krow0 + r)*D_ + h*DH_ + dq);
        }
        __syncthreads();

        float s[4][4];
        #pragma unroll
        for (int r = 0; r < 4; r++)
            #pragma unroll
            for (int c = 0; c < 4; c++) s[r][c] = 0.f;
        #pragma unroll 16
        for (int d = 0; d < 64; d++) {
            const float4 aq = *(const float4*)(Qst + d*SROW + ty*4);
            const float4 bk = *(const float4*)(Kst + d*SROW + tx*4);
            const float a[4] = {aq.x, aq.y, aq.z, aq.w};
            const float bb[4] = {bk.x, bk.y, bk.z, bk.w};
            #pragma unroll
            for (int r = 0; r < 4; r++)
                #pragma unroll
                for (int c = 0; c < 4; c++) s[r][c] += a[r] * bb[c];
        }

        const int ig0 = qb*64 + ty*4;
        const int jg0 = kb*64 + tx*4;
        #pragma unroll
        for (int r = 0; r < 4; r++)
            #pragma unroll
            for (int c = 0; c < 4; c++) {
                const int dist = (ig0 + r) - (jg0 + c);
                if (dist < 0) s[r][c] = -1e30f;
                else          s[r][c] += rel_s[dist > MAXREL ? MAXREL : dist];
            }

        float alpha[4];
        #pragma unroll
        for (int r = 0; r < 4; r++) {
            float mx = fmaxf(fmaxf(s[r][0], s[r][1]), fmaxf(s[r][2], s[r][3]));
            #pragma unroll
            for (int off = 8; off; off >>= 1)
                mx = fmaxf(mx, __shfl_xor_sync(0xffffffffu, mx, off));
            const float mnew = fmaxf(mreg[r], mx);
            alpha[r] = __expf(mreg[r] - mnew);
            float rsum = 0.f;
            #pragma unroll
            for (int c = 0; c < 4; c++) {
                const float p = __expf(s[r][c] - mnew);
                s[r][c] = p;
                rsum += p;
            }
            #pragma unroll
            for (int off = 8; off; off >>= 1)
                rsum += __shfl_xor_sync(0xffffffffu, rsum, off);
            lreg[r] = lreg[r] * alpha[r] + rsum;
            mreg[r] = mnew;
            #pragma unroll
            for (int c = 0; c < 4; c++) o[r][c] *= alpha[r];
        }

        #pragma unroll
        for (int c = 0; c < 4; c++)
            *(float4*)(Pst + (tx*4+c)*SROW + ty*4) =
                make_float4(s[0][c], s[1][c], s[2][c], s[3][c]);
        __syncthreads();

        #pragma unroll 16
        for (int j = 0; j < 64; j++) {
            const float4 pv = *(const float4*)(Pst + j*SROW + ty*4);
            const float4 vv = *(const float4*)(Vs  + j*SROW + tx*4);
            const float p[4] = {pv.x, pv.y, pv.z, pv.w};
            const float vb[4] = {vv.x, vv.y, vv.z, vv.w};
            #pragma unroll
            for (int r = 0; r < 4; r++)
                #pragma unroll
                for (int c = 0; c < 4; c++) o[r][c] += p[r] * vb[c];
        }
    }

    #pragma unroll
    for (int r = 0; r < 4; r++) {
        const float inv = 1.0f / lreg[r];
        const int ig = qb*64 + ty*4 + r;
        *(float4*)(y + (size_t)(b*T_ + ig)*D_ + h*DH_ + tx*4) =
            make_float4(o[r][0]*inv, o[r][1]*inv, o[r][2]*inv, o[r][3]*inv);
    }
}

#define ATTN_SMEM ((4*64*SROW + 132) * (int)sizeof(float))

extern "C" void kernel_launch(void* const* d_in, const int* in_sizes, int n_in,
                              void* d_out, int out_size)
{
    const float* x     = (const float*)d_in[0];
    const float* Wq    = (const float*)d_in[1];
    const float* Wk    = (const float*)d_in[2];
    const float* Wv    = (const float*)d_in[3];
    const float* Wo    = (const float*)d_in[4];
    const float* rel   = (const float*)d_in[5];
    const float* gamma = (const float*)d_in[6];
    const float* beta  = (const float*)d_in[7];
    float* out = (float*)d_out;

    float *p_xn, *p_q, *p_k, *p_v, *p_y;
    cudaGetSymbolAddress((void**)&p_xn, g_xn);
    cudaGetSymbolAddress((void**)&p_q,  g_q);
    cudaGetSymbolAddress((void**)&p_k,  g_k);
    cudaGetSymbolAddress((void**)&p_v,  g_v);
    cudaGetSymbolAddress((void**)&p_y,  g_y);

    cudaFuncSetAttribute(attn_kernel, cudaFuncAttributeMaxDynamicSharedMemorySize, ATTN_SMEM);

    ln_kernel<<<M_, 256>>>(x, gamma, beta, p_xn);
    qkv_kernel<<<dim3(D_/128, M_/128, 3), 256>>>(p_xn, Wq, Wk, Wv, p_q, p_k, p_v);
    attn_kernel<<<dim3(T_/64, H_, B_), 256, ATTN_SMEM>>>(p_q, p_k, p_v, rel, p_y);
    out_kernel<<<dim3(D_/128, M_/128), 256>>>(p_y, Wo, x, out);
}

// round 4
// speedup vs baseline: 1.6977x; 1.6977x over previous
#include <cuda_runtime.h>
#include <cuda_bf16.h>
#include <math.h>
#include <stdint.h>

#define B_  4
#define T_  2048
#define D_  1024
#define H_  16
#define DH_ 64
#define M_  (B_*T_)      // 8192 rows
#define MAXREL 128

// ---------------- scratch (device globals; no allocs allowed) ----------------
__device__ __nv_bfloat16 g_xnh[M_*D_], g_xnl[M_*D_];     // LN output, split bf16
__device__ __nv_bfloat16 g_wh[4*D_*D_], g_wl[4*D_*D_];   // Wq,Wk,Wv,Wo split
__device__ __nv_bfloat16 g_yh[M_*D_],  g_yl[M_*D_];      // attention output, split
__device__ float g_q[M_*D_], g_k[M_*D_], g_v[M_*D_];

__device__ __forceinline__ uint32_t bf2_pack(__nv_bfloat16 a, __nv_bfloat16 b)
{
    __nv_bfloat162 p = __halves2bfloat162(a, b);
    return *reinterpret_cast<uint32_t*>(&p);
}

__device__ __forceinline__ void split4(const float* v, uint32_t& h01, uint32_t& h23,
                                       uint32_t& l01, uint32_t& l23)
{
    __nv_bfloat16 h[4], l[4];
    #pragma unroll
    for (int e = 0; e < 4; e++) {
        h[e] = __float2bfloat16_rn(v[e]);
        l[e] = __float2bfloat16_rn(v[e] - __bfloat162float(h[e]));
    }
    h01 = bf2_pack(h[0], h[1]); h23 = bf2_pack(h[2], h[3]);
    l01 = bf2_pack(l[0], l[1]); l23 = bf2_pack(l[2], l[3]);
}

// ---------------- LayerNorm: one block per row, writes split bf16 ------------
__global__ void ln_kernel(const float* __restrict__ x, const float* __restrict__ gamma,
                          const float* __restrict__ beta,
                          __nv_bfloat16* __restrict__ xnh, __nv_bfloat16* __restrict__ xnl)
{
    const int row = blockIdx.x;
    const int tid = threadIdx.x;              // 256 threads, 4 floats each
    const float4 v = *(const float4*)(x + (size_t)row*D_ + tid*4);
    float s  = v.x + v.y + v.z + v.w;
    float ss = v.x*v.x + v.y*v.y + v.z*v.z + v.w*v.w;
    #pragma unroll
    for (int off = 16; off; off >>= 1) {
        s  += __shfl_xor_sync(0xffffffffu, s,  off);
        ss += __shfl_xor_sync(0xffffffffu, ss, off);
    }
    __shared__ float sh_s[8], sh_ss[8];
    const int w = tid >> 5;
    if ((tid & 31) == 0) { sh_s[w] = s; sh_ss[w] = ss; }
    __syncthreads();
    float ts = 0.f, tss = 0.f;
    #pragma unroll
    for (int i = 0; i < 8; i++) { ts += sh_s[i]; tss += sh_ss[i]; }
    const float mu   = ts * (1.0f / D_);
    const float var  = tss * (1.0f / D_) - mu * mu;
    const float rstd = rsqrtf(var + 1e-5f);
    const float4 gv = *(const float4*)(gamma + tid*4);
    const float4 bv = *(const float4*)(beta  + tid*4);
    float o[4];
    o[0] = (v.x - mu) * rstd * gv.x + bv.x;
    o[1] = (v.y - mu) * rstd * gv.y + bv.y;
    o[2] = (v.z - mu) * rstd * gv.z + bv.z;
    o[3] = (v.w - mu) * rstd * gv.w + bv.w;
    uint32_t h01, h23, l01, l23;
    split4(o, h01, h23, l01, l23);
    *(uint2*)(xnh + (size_t)row*D_ + tid*4) = make_uint2(h01, h23);
    *(uint2*)(xnl + (size_t)row*D_ + tid*4) = make_uint2(l01, l23);
}

// ---------------- Weight split: 4 matrices, fp32 -> (hi, lo) bf16 ------------
__global__ void wsplit_kernel(const float* __restrict__ Wq, const float* __restrict__ Wk,
                              const float* __restrict__ Wv, const float* __restrict__ Wo,
                              __nv_bfloat16* __restrict__ wh, __nv_bfloat16* __restrict__ wl)
{
    const int z = blockIdx.y;
    const float* W = (z == 0) ? Wq : (z == 1) ? Wk : (z == 2) ? Wv : Wo;
    const size_t base = (size_t)z * D_ * D_;
    const size_t idx = ((size_t)blockIdx.x * 256 + threadIdx.x) * 4;
    const float4 v = *(const float4*)(W + idx);
    const float vv[4] = {v.x, v.y, v.z, v.w};
    uint32_t h01, h23, l01, l23;
    split4(vv, h01, h23, l01, l23);
    *(uint2*)(wh + base + idx) = make_uint2(h01, h23);
    *(uint2*)(wl + base + idx) = make_uint2(l01, l23);
}

// ---------------- Tensor-core GEMM (split-bf16, 3-pass, cp.async) ------------
// C[m][n] = scale * sum_k A[m][k]*B[n][k]  (+ res[m][n] if RES)
// CTA 128x128, BK=32, 256 threads = 8 warps (4x2), warp tile 32x64.

__device__ __forceinline__ void mma16816(float* d, const uint32_t* a, const uint32_t* b)
{
    asm volatile(
        "mma.sync.aligned.m16n8k16.row.col.f32.bf16.bf16.f32 "
        "{%0,%1,%2,%3}, {%4,%5,%6,%7}, {%8,%9}, {%0,%1,%2,%3};\n"
        : "+f"(d[0]), "+f"(d[1]), "+f"(d[2]), "+f"(d[3])
        : "r"(a[0]), "r"(a[1]), "r"(a[2]), "r"(a[3]), "r"(b[0]), "r"(b[1]));
}

#define CPA16(dst, src) asm volatile("cp.async.cg.shared.global [%0], [%1], 16;\n" :: "r"(dst), "l"(src))
#define CPA_COMMIT()    asm volatile("cp.async.commit_group;\n" ::)
#define CPA_WAIT1()     asm volatile("cp.async.wait_group 1;\n" ::)
#define CPA_WAIT0()     asm volatile("cp.async.wait_group 0;\n" ::)

#define GSTRIDE 20                         // smem row stride in words (conflict-free)
#define ARR_W   (128*GSTRIDE)              // words per array
#define GEMM_SMEM (2*4*ARR_W*4)            // 81920 bytes

template<bool RES>
__device__ __forceinline__ void mma_gemm_body(
    const __nv_bfloat16* __restrict__ Ah, const __nv_bfloat16* __restrict__ Al,
    const __nv_bfloat16* __restrict__ Bh, const __nv_bfloat16* __restrict__ Bl,
    float* __restrict__ C, const float* __restrict__ res, float scale)
{
    extern __shared__ uint32_t smw[];
    const uint32_t sbase = (uint32_t)__cvta_generic_to_shared(smw);

    const int tid  = threadIdx.x;
    const int warp = tid >> 5, lane = tid & 31;
    const int wm = warp >> 1, wn = warp & 1;        // 4x2 warp grid
    const int g  = lane >> 2, t = lane & 3;
    const int m0 = blockIdx.y * 128, n0 = blockIdx.x * 128;

    float acc[2][8][4];
    #pragma unroll
    for (int i = 0; i < 2; i++)
        #pragma unroll
        for (int j = 0; j < 8; j++)
            #pragma unroll
            for (int c = 0; c < 4; c++) acc[i][j][c] = 0.f;

    // cp.async loader: 2 chunks x 4 arrays per thread per stage
    auto LOAD = [&](int k0, int st) {
        #pragma unroll
        for (int half = 0; half < 2; half++) {
            const int c   = tid + half * 256;       // 0..511
            const int row = c >> 2;
            const int w0  = (c & 3) * 4;            // word col: 0,4,8,12
            const size_t ga = (size_t)(m0 + row) * D_ + k0 + w0 * 2;
            const size_t gb = (size_t)(n0 + row) * D_ + k0 + w0 * 2;
            const uint32_t dbase = sbase + (uint32_t)((st * 4 * ARR_W) + row * GSTRIDE + w0) * 4;
            CPA16(dbase + 0 * ARR_W * 4, Ah + ga);
            CPA16(dbase + 1 * ARR_W * 4, Al + ga);
            CPA16(dbase + 2 * ARR_W * 4, Bh + gb);
            CPA16(dbase + 3 * ARR_W * 4, Bl + gb);
        }
    };

    LOAD(0, 0);
    CPA_COMMIT();

    for (int it = 0; it < D_ / 32; it++) {
        const int cur = it & 1;
        if (it + 1 < D_ / 32) {
            LOAD((it + 1) * 32, cur ^ 1);
            CPA_COMMIT();
            CPA_WAIT1();
        } else {
            CPA_WAIT0();
        }
        __syncthreads();

        const uint32_t* sAh = smw + cur * 4 * ARR_W;
        const uint32_t* sAl = sAh + ARR_W;
        const uint32_t* sBh = sAl + ARR_W;
        const uint32_t* sBl = sBh + ARR_W;

        #pragma unroll
        for (int ks = 0; ks < 2; ks++) {
            const int w0 = ks * 8 + t;
            uint32_t ah[2][4], al[2][4];
            #pragma unroll
            for (int i = 0; i < 2; i++) {
                const int r = wm * 32 + i * 16 + g;
                ah[i][0] = sAh[r*GSTRIDE + w0];       ah[i][1] = sAh[(r+8)*GSTRIDE + w0];
                ah[i][2] = sAh[r*GSTRIDE + w0 + 4];   ah[i][3] = sAh[(r+8)*GSTRIDE + w0 + 4];
                al[i][0] = sAl[r*GSTRIDE + w0];       al[i][1] = sAl[(r+8)*GSTRIDE + w0];
                al[i][2] = sAl[r*GSTRIDE + w0 + 4];   al[i][3] = sAl[(r+8)*GSTRIDE + w0 + 4];
            }
            #pragma unroll
            for (int j = 0; j < 8; j++) {
                const int n = wn * 64 + j * 8 + g;
                const uint32_t bhf[2] = {sBh[n*GSTRIDE + w0], sBh[n*GSTRIDE + w0 + 4]};
                const uint32_t blf[2] = {sBl[n*GSTRIDE + w0], sBl[n*GSTRIDE + w0 + 4]};
                #pragma unroll
                for (int i = 0; i < 2; i++) {
                    mma16816(acc[i][j], ah[i], bhf);
                    mma16816(acc[i][j], al[i], bhf);
                    mma16816(acc[i][j], ah[i], blf);
                }
            }
        }
        __syncthreads();
    }

    // epilogue
    #pragma unroll
    for (int i = 0; i < 2; i++) {
        const int r0 = m0 + wm * 32 + i * 16 + g;
        #pragma unroll
        for (int j = 0; j < 8; j++) {
            const int c = n0 + wn * 64 + j * 8 + 2 * t;
            float2 v0 = make_float2(acc[i][j][0] * scale, acc[i][j][1] * scale);
            float2 v1 = make_float2(acc[i][j][2] * scale, acc[i][j][3] * scale);
            if (RES) {
                const float2 r0v = *(const float2*)(res + (size_t)r0 * D_ + c);
                const float2 r1v = *(const float2*)(res + (size_t)(r0+8) * D_ + c);
                v0.x += r0v.x; v0.y += r0v.y;
                v1.x += r1v.x; v1.y += r1v.y;
            }
            *(float2*)(C + (size_t)r0     * D_ + c) = v0;
            *(float2*)(C + (size_t)(r0+8) * D_ + c) = v1;
        }
    }
}

// QKV fused (blockIdx.z selects W); q scaled by 1/sqrt(DH)=0.125
__global__ __launch_bounds__(256, 2)
void qkv_kernel(const __nv_bfloat16* __restrict__ xnh, const __nv_bfloat16* __restrict__ xnl,
                const __nv_bfloat16* __restrict__ wh,  const __nv_bfloat16* __restrict__ wl,
                float* __restrict__ q, float* __restrict__ k, float* __restrict__ v)
{
    const int z = blockIdx.z;
    float* C = (z == 0) ? q : (z == 1) ? k : v;
    const float scale = (z == 0) ? 0.125f : 1.0f;
    const size_t off = (size_t)z * D_ * D_;
    mma_gemm_body<false>(xnh, xnl, wh + off, wl + off, C, nullptr, scale);
}

__global__ __launch_bounds__(256, 2)
void out_kernel(const __nv_bfloat16* __restrict__ yh, const __nv_bfloat16* __restrict__ yl,
                const __nv_bfloat16* __restrict__ wh, const __nv_bfloat16* __restrict__ wl,
                const float* __restrict__ x, float* __restrict__ out)
{
    const size_t off = (size_t)3 * D_ * D_;
    mma_gemm_body<true>(yh, yl, wh + off, wl + off, out, x, 1.0f);
}

// ---------------- Flash attention with causal mask + relative bias -----------
// Grid: (32 qblocks, 16 heads, 4 batch), 256 threads.
#define SROW 68   // padded row stride
__global__ void attn_kernel(const float* __restrict__ q, const float* __restrict__ k,
                            const float* __restrict__ v, const float* __restrict__ rel,
                            __nv_bfloat16* __restrict__ yh, __nv_bfloat16* __restrict__ yl)
{
    extern __shared__ float sm[];
    float* Qst   = sm;                  // [d][i] 64xSROW
    float* Kst   = sm + 64*SROW;        // [d][j]
    float* Pst   = sm + 2*64*SROW;      // [j][i]
    float* Vs    = sm + 3*64*SROW;      // [j][d]
    float* rel_s = sm + 4*64*SROW;      // 129

    const int qb = 31 - (int)blockIdx.x;   // heavy blocks first
    const int h  = blockIdx.y;
    const int b  = blockIdx.z;
    const int tid = threadIdx.x;
    const int tx = tid & 15, ty = tid >> 4;

    for (int i = tid; i <= MAXREL; i += 256) rel_s[i] = rel[h*(MAXREL+1) + i];

    const int qrow0 = b*T_ + qb*64;
    #pragma unroll
    for (int it = 0; it < 4; it++) {
        const int f4 = tid + it*256;
        const int r  = f4 >> 4;
        const int dq = (f4 & 15) * 4;
        const float4 val = *(const float4*)(q + (size_t)(qrow0 + r)*D_ + h*DH_ + dq);
        Qst[(dq+0)*SROW + r] = val.x;
        Qst[(dq+1)*SROW + r] = val.y;
        Qst[(dq+2)*SROW + r] = val.z;
        Qst[(dq+3)*SROW + r] = val.w;
    }

    float mreg[4], lreg[4], o[4][4];
    #pragma unroll
    for (int r = 0; r < 4; r++) {
        mreg[r] = -1e30f; lreg[r] = 0.f;
        #pragma unroll
        for (int c = 0; c < 4; c++) o[r][c] = 0.f;
    }

    for (int kb = 0; kb <= qb; kb++) {
        __syncthreads();
        const int krow0 = b*T_ + kb*64;
        #pragma unroll
        for (int it = 0; it < 4; it++) {
            const int f4 = tid + it*256;
            const int r  = f4 >> 4;
            const int dq = (f4 & 15) * 4;
            const float4 kv = *(const float4*)(k + (size_t)(krow0 + r)*D_ + h*DH_ + dq);
            Kst[(dq+0)*SROW + r] = kv.x;
            Kst[(dq+1)*SROW + r] = kv.y;
            Kst[(dq+2)*SROW + r] = kv.z;
            Kst[(dq+3)*SROW + r] = kv.w;
            *(float4*)(Vs + (size_t)r*SROW + dq) =
                *(const float4*)(v + (size_t)(krow0 + r)*D_ + h*DH_ + dq);
        }
        __syncthreads();

        float s[4][4];
        #pragma unroll
        for (int r = 0; r < 4; r++)
            #pragma unroll
            for (int c = 0; c < 4; c++) s[r][c] = 0.f;
        #pragma unroll 16
        for (int d = 0; d < 64; d++) {
            const float4 aq = *(const float4*)(Qst + d*SROW + ty*4);
            const float4 bk = *(const float4*)(Kst + d*SROW + tx*4);
            const float a[4] = {aq.x, aq.y, aq.z, aq.w};
            const float bb[4] = {bk.x, bk.y, bk.z, bk.w};
            #pragma unroll
            for (int r = 0; r < 4; r++)
                #pragma unroll
                for (int c = 0; c < 4; c++) s[r][c] += a[r] * bb[c];
        }

        const int ig0 = qb*64 + ty*4;
        const int jg0 = kb*64 + tx*4;
        #pragma unroll
        for (int r = 0; r < 4; r++)
            #pragma unroll
            for (int c = 0; c < 4; c++) {
                const int dist = (ig0 + r) - (jg0 + c);
                if (dist < 0) s[r][c] = -1e30f;
                else          s[r][c] += rel_s[dist > MAXREL ? MAXREL : dist];
            }

        float alpha[4];
        #pragma unroll
        for (int r = 0; r < 4; r++) {
            float mx = fmaxf(fmaxf(s[r][0], s[r][1]), fmaxf(s[r][2], s[r][3]));
            #pragma unroll
            for (int off = 8; off; off >>= 1)
                mx = fmaxf(mx, __shfl_xor_sync(0xffffffffu, mx, off));
            const float mnew = fmaxf(mreg[r], mx);
            alpha[r] = __expf(mreg[r] - mnew);
            float rsum = 0.f;
            #pragma unroll
            for (int c = 0; c < 4; c++) {
                const float p = __expf(s[r][c] - mnew);
                s[r][c] = p;
                rsum += p;
            }
            #pragma unroll
            for (int off = 8; off; off >>= 1)
                rsum += __shfl_xor_sync(0xffffffffu, rsum, off);
            lreg[r] = lreg[r] * alpha[r] + rsum;
            mreg[r] = mnew;
            #pragma unroll
            for (int c = 0; c < 4; c++) o[r][c] *= alpha[r];
        }

        #pragma unroll
        for (int c = 0; c < 4; c++)
            *(float4*)(Pst + (tx*4+c)*SROW + ty*4) =
                make_float4(s[0][c], s[1][c], s[2][c], s[3][c]);
        __syncthreads();

        #pragma unroll 16
        for (int j = 0; j < 64; j++) {
            const float4 pv = *(const float4*)(Pst + j*SROW + ty*4);
            const float4 vv = *(const float4*)(Vs  + j*SROW + tx*4);
            const float p[4] = {pv.x, pv.y, pv.z, pv.w};
            const float vb[4] = {vv.x, vv.y, vv.z, vv.w};
            #pragma unroll
            for (int r = 0; r < 4; r++)
                #pragma unroll
                for (int c = 0; c < 4; c++) o[r][c] += p[r] * vb[c];
        }
    }

    #pragma unroll
    for (int r = 0; r < 4; r++) {
        const float inv = 1.0f / lreg[r];
        const int ig = qb*64 + ty*4 + r;
        const float vals[4] = {o[r][0]*inv, o[r][1]*inv, o[r][2]*inv, o[r][3]*inv};
        uint32_t h01, h23, l01, l23;
        split4(vals, h01, h23, l01, l23);
        const size_t base = (size_t)(b*T_ + ig)*D_ + h*DH_ + tx*4;
        *(uint2*)(yh + base) = make_uint2(h01, h23);
        *(uint2*)(yl + base) = make_uint2(l01, l23);
    }
}

#define ATTN_SMEM ((4*64*SROW + 132) * (int)sizeof(float))

extern "C" void kernel_launch(void* const* d_in, const int* in_sizes, int n_in,
                              void* d_out, int out_size)
{
    const float* x     = (const float*)d_in[0];
    const float* Wq    = (const float*)d_in[1];
    const float* Wk    = (const float*)d_in[2];
    const float* Wv    = (const float*)d_in[3];
    const float* Wo    = (const float*)d_in[4];
    const float* rel   = (const float*)d_in[5];
    const float* gamma = (const float*)d_in[6];
    const float* beta  = (const float*)d_in[7];
    float* out = (float*)d_out;

    __nv_bfloat16 *p_xnh, *p_xnl, *p_wh, *p_wl, *p_yh, *p_yl;
    float *p_q, *p_k, *p_v;
    cudaGetSymbolAddress((void**)&p_xnh, g_xnh);
    cudaGetSymbolAddress((void**)&p_xnl, g_xnl);
    cudaGetSymbolAddress((void**)&p_wh,  g_wh);
    cudaGetSymbolAddress((void**)&p_wl,  g_wl);
    cudaGetSymbolAddress((void**)&p_yh,  g_yh);
    cudaGetSymbolAddress((void**)&p_yl,  g_yl);
    cudaGetSymbolAddress((void**)&p_q,   g_q);
    cudaGetSymbolAddress((void**)&p_k,   g_k);
    cudaGetSymbolAddress((void**)&p_v,   g_v);

    cudaFuncSetAttribute(qkv_kernel, cudaFuncAttributeMaxDynamicSharedMemorySize, GEMM_SMEM);
    cudaFuncSetAttribute(out_kernel, cudaFuncAttributeMaxDynamicSharedMemorySize, GEMM_SMEM);
    cudaFuncSetAttribute(attn_kernel, cudaFuncAttributeMaxDynamicSharedMemorySize, ATTN_SMEM);

    ln_kernel<<<M_, 256>>>(x, gamma, beta, p_xnh, p_xnl);
    wsplit_kernel<<<dim3(D_*D_/(256*4), 4), 256>>>(Wq, Wk, Wv, Wo, p_wh, p_wl);
    qkv_kernel<<<dim3(D_/128, M_/128, 3), 256, GEMM_SMEM>>>(p_xnh, p_xnl, p_wh, p_wl, p_q, p_k, p_v);
    attn_kernel<<<dim3(T_/64, H_, B_), 256, ATTN_SMEM>>>(p_q, p_k, p_v, rel, p_yh, p_yl);
    out_kernel<<<dim3(D_/128, M_/128), 256, GEMM_SMEM>>>(p_yh, p_yl, p_wh, p_wl, x, out);
}

// round 8
// speedup vs baseline: 3.0524x; 1.7979x over previous
#include <cuda_runtime.h>
#include <cuda_bf16.h>
#include <math.h>
#include <stdint.h>

#define B_  4
#define T_  2048
#define D_  1024
#define H_  16
#define DH_ 64
#define M_  (B_*T_)      // 8192 rows
#define MAXREL 128
#define DD_ (D_*D_)

// ---------------- scratch (device globals; no allocs allowed) ----------------
__device__ __nv_bfloat16 g_xnh[M_*D_], g_xnl[M_*D_];     // LN output, split bf16
__device__ __nv_bfloat16 g_wh[4*DD_],  g_wl[4*DD_];      // Wq,Wk,Wv,Wo split
__device__ __nv_bfloat16 g_yh[M_*D_],  g_yl[M_*D_];      // attention output, split
__device__ __nv_bfloat16 g_qh[M_*D_],  g_ql[M_*D_];
__device__ __nv_bfloat16 g_kh[M_*D_],  g_kl[M_*D_];
__device__ __nv_bfloat16 g_vh[M_*D_],  g_vl[M_*D_];

// ---------------- helpers ----------------
__device__ __forceinline__ uint32_t bf2_pack(__nv_bfloat16 a, __nv_bfloat16 b)
{
    __nv_bfloat162 p = __halves2bfloat162(a, b);   // a -> low 16 bits
    return *reinterpret_cast<uint32_t*>(&p);
}

__device__ __forceinline__ void split2pack(float a, float b, uint32_t& hp, uint32_t& lp)
{
    __nv_bfloat16 ah = __float2bfloat16_rn(a), bh = __float2bfloat16_rn(b);
    __nv_bfloat16 al = __float2bfloat16_rn(a - __bfloat162float(ah));
    __nv_bfloat16 bl = __float2bfloat16_rn(b - __bfloat162float(bh));
    hp = bf2_pack(ah, bh);
    lp = bf2_pack(al, bl);
}

__device__ __forceinline__ void split4(const float* v, uint32_t& h01, uint32_t& h23,
                                       uint32_t& l01, uint32_t& l23)
{
    split2pack(v[0], v[1], h01, l01);
    split2pack(v[2], v[3], h23, l23);
}

__device__ __forceinline__ uint32_t sm_u32(const void* p)
{
    uint32_t a;
    asm("{ .reg .u64 t; cvta.to.shared.u64 t, %1; cvt.u32.u64 %0, t; }" : "=r"(a) : "l"(p));
    return a;
}

__device__ __forceinline__ void mma16816(float* d, const uint32_t* a, const uint32_t* b)
{
    asm volatile(
        "mma.sync.aligned.m16n8k16.row.col.f32.bf16.bf16.f32 "
        "{%0,%1,%2,%3}, {%4,%5,%6,%7}, {%8,%9}, {%0,%1,%2,%3};\n"
        : "+f"(d[0]), "+f"(d[1]), "+f"(d[2]), "+f"(d[3])
        : "r"(a[0]), "r"(a[1]), "r"(a[2]), "r"(a[3]), "r"(b[0]), "r"(b[1]));
}

#define CPA16(dst, src) asm volatile("cp.async.cg.shared.global [%0], [%1], 16;\n" :: "r"(dst), "l"(src))
#define CPA_COMMIT()    asm volatile("cp.async.commit_group;\n" ::)
#define CPA_WAIT1()     asm volatile("cp.async.wait_group 1;\n" ::)
#define CPA_WAIT0()     asm volatile("cp.async.wait_group 0;\n" ::)

#define LDSM4(R, a) asm volatile( \
    "ldmatrix.sync.aligned.m8n8.x4.shared.b16 {%0,%1,%2,%3}, [%4];" \
    : "=r"((R)[0]), "=r"((R)[1]), "=r"((R)[2]), "=r"((R)[3]) : "r"(a))
#define LDSM4T(R, a) asm volatile( \
    "ldmatrix.sync.aligned.m8n8.x4.trans.shared.b16 {%0,%1,%2,%3}, [%4];" \
    : "=r"((R)[0]), "=r"((R)[1]), "=r"((R)[2]), "=r"((R)[3]) : "r"(a))

#define SMEM_SWZ(o) ((uint32_t)(o) ^ ((((uint32_t)(o)) >> 3) & 0x70u))

// ---------------- LayerNorm: one block per row, writes split bf16 ------------
__global__ void ln_kernel(const float* __restrict__ x, const float* __restrict__ gamma,
                          const float* __restrict__ beta,
                          __nv_bfloat16* __restrict__ xnh, __nv_bfloat16* __restrict__ xnl)
{
    const int row = blockIdx.x;
    const int tid = threadIdx.x;
    const float4 v = *(const float4*)(x + (size_t)row*D_ + tid*4);
    float s  = v.x + v.y + v.z + v.w;
    float ss = v.x*v.x + v.y*v.y + v.z*v.z + v.w*v.w;
    #pragma unroll
    for (int off = 16; off; off >>= 1) {
        s  += __shfl_xor_sync(0xffffffffu, s,  off);
        ss += __shfl_xor_sync(0xffffffffu, ss, off);
    }
    __shared__ float sh_s[8], sh_ss[8];
    const int w = tid >> 5;
    if ((tid & 31) == 0) { sh_s[w] = s; sh_ss[w] = ss; }
    __syncthreads();
    float ts = 0.f, tss = 0.f;
    #pragma unroll
    for (int i = 0; i < 8; i++) { ts += sh_s[i]; tss += sh_ss[i]; }
    const float mu   = ts * (1.0f / D_);
    const float var  = tss * (1.0f / D_) - mu * mu;
    const float rstd = rsqrtf(var + 1e-5f);
    const float4 gv = *(const float4*)(gamma + tid*4);
    const float4 bv = *(const float4*)(beta  + tid*4);
    float o[4];
    o[0] = (v.x - mu) * rstd * gv.x + bv.x;
    o[1] = (v.y - mu) * rstd * gv.y + bv.y;
    o[2] = (v.z - mu) * rstd * gv.z + bv.z;
    o[3] = (v.w - mu) * rstd * gv.w + bv.w;
    uint32_t h01, h23, l01, l23;
    split4(o, h01, h23, l01, l23);
    *(uint2*)(xnh + (size_t)row*D_ + tid*4) = make_uint2(h01, h23);
    *(uint2*)(xnl + (size_t)row*D_ + tid*4) = make_uint2(l01, l23);
}

// ---------------- Weight split ----------------
__global__ void wsplit_kernel(const float* __restrict__ Wq, const float* __restrict__ Wk,
                              const float* __restrict__ Wv, const float* __restrict__ Wo,
                              __nv_bfloat16* __restrict__ wh, __nv_bfloat16* __restrict__ wl)
{
    const int z = blockIdx.y;
    const float* W = (z == 0) ? Wq : (z == 1) ? Wk : (z == 2) ? Wv : Wo;
    const size_t base = (size_t)z * DD_;
    const size_t idx = ((size_t)blockIdx.x * 256 + threadIdx.x) * 4;
    const float4 v = *(const float4*)(W + idx);
    const float vv[4] = {v.x, v.y, v.z, v.w};
    uint32_t h01, h23, l01, l23;
    split4(vv, h01, h23, l01, l23);
    *(uint2*)(wh + base + idx) = make_uint2(h01, h23);
    *(uint2*)(wl + base + idx) = make_uint2(l01, l23);
}

// ---------------- HMMA GEMM (split-bf16, 3-pass, cp.async) -------------------
// C = scale*(A @ W^T) (+res).  CTA 128x128, BK=32, 256 thr = 8 warps (4x2).
// MODE 0: fp32 out + residual.  MODE 1: split-bf16 out (Ch, Cl).
#define GSTRIDE 20
#define ARR_W   (128*GSTRIDE)
#define GEMM_SMEM (2*4*ARR_W*4)

template<int MODE>
__device__ __forceinline__ void mma_gemm_body(
    const __nv_bfloat16* __restrict__ Ah, const __nv_bfloat16* __restrict__ Al,
    const __nv_bfloat16* __restrict__ Bh, const __nv_bfloat16* __restrict__ Bl,
    float* __restrict__ Cf, const float* __restrict__ res,
    __nv_bfloat16* __restrict__ Ch, __nv_bfloat16* __restrict__ Cl, float scale)
{
    extern __shared__ uint32_t smw[];
    const uint32_t sbase = (uint32_t)__cvta_generic_to_shared(smw);

    const int tid  = threadIdx.x;
    const int warp = tid >> 5, lane = tid & 31;
    const int wm = warp >> 1, wn = warp & 1;
    const int g  = lane >> 2, t = lane & 3;
    const int m0 = blockIdx.y * 128, n0 = blockIdx.x * 128;

    float acc[2][8][4];
    #pragma unroll
    for (int i = 0; i < 2; i++)
        #pragma unroll
        for (int j = 0; j < 8; j++)
            #pragma unroll
            for (int c = 0; c < 4; c++) acc[i][j][c] = 0.f;

    auto LOAD = [&](int k0, int st) {
        #pragma unroll
        for (int half = 0; half < 2; half++) {
            const int c   = tid + half * 256;
            const int row = c >> 2;
            const int w0  = (c & 3) * 4;
            const size_t ga = (size_t)(m0 + row) * D_ + k0 + w0 * 2;
            const size_t gb = (size_t)(n0 + row) * D_ + k0 + w0 * 2;
            const uint32_t dbase = sbase + (uint32_t)((st * 4 * ARR_W) + row * GSTRIDE + w0) * 4;
            CPA16(dbase + 0 * ARR_W * 4, Ah + ga);
            CPA16(dbase + 1 * ARR_W * 4, Al + ga);
            CPA16(dbase + 2 * ARR_W * 4, Bh + gb);
            CPA16(dbase + 3 * ARR_W * 4, Bl + gb);
        }
    };

    LOAD(0, 0);
    CPA_COMMIT();

    for (int it = 0; it < D_ / 32; it++) {
        const int cur = it & 1;
        if (it + 1 < D_ / 32) {
            LOAD((it + 1) * 32, cur ^ 1);
            CPA_COMMIT();
            CPA_WAIT1();
        } else {
            CPA_WAIT0();
        }
        __syncthreads();

        const uint32_t* sAh = smw + cur * 4 * ARR_W;
        const uint32_t* sAl = sAh + ARR_W;
        const uint32_t* sBh = sAl + ARR_W;
        const uint32_t* sBl = sBh + ARR_W;

        #pragma unroll
        for (int ks = 0; ks < 2; ks++) {
            const int w0 = ks * 8 + t;
            uint32_t ah[2][4], al[2][4];
            #pragma unroll
            for (int i = 0; i < 2; i++) {
                const int r = wm * 32 + i * 16 + g;
                ah[i][0] = sAh[r*GSTRIDE + w0];       ah[i][1] = sAh[(r+8)*GSTRIDE + w0];
                ah[i][2] = sAh[r*GSTRIDE + w0 + 4];   ah[i][3] = sAh[(r+8)*GSTRIDE + w0 + 4];
                al[i][0] = sAl[r*GSTRIDE + w0];       al[i][1] = sAl[(r+8)*GSTRIDE + w0];
                al[i][2] = sAl[r*GSTRIDE + w0 + 4];   al[i][3] = sAl[(r+8)*GSTRIDE + w0 + 4];
            }
            #pragma unroll
            for (int j = 0; j < 8; j++) {
                const int n = wn * 64 + j * 8 + g;
                const uint32_t bhf[2] = {sBh[n*GSTRIDE + w0], sBh[n*GSTRIDE + w0 + 4]};
                const uint32_t blf[2] = {sBl[n*GSTRIDE + w0], sBl[n*GSTRIDE + w0 + 4]};
                #pragma unroll
                for (int i = 0; i < 2; i++) {
                    mma16816(acc[i][j], ah[i], bhf);
                    mma16816(acc[i][j], al[i], bhf);
                    mma16816(acc[i][j], ah[i], blf);
                }
            }
        }
        __syncthreads();
    }

    #pragma unroll
    for (int i = 0; i < 2; i++) {
        const int r0 = m0 + wm * 32 + i * 16 + g;
        #pragma unroll
        for (int j = 0; j < 8; j++) {
            const int c = n0 + wn * 64 + j * 8 + 2 * t;
            const float x0 = acc[i][j][0] * scale, x1 = acc[i][j][1] * scale;
            const float x2 = acc[i][j][2] * scale, x3 = acc[i][j][3] * scale;
            if (MODE == 0) {
                const float2 r0v = *(const float2*)(res + (size_t)r0 * D_ + c);
                const float2 r1v = *(const float2*)(res + (size_t)(r0+8) * D_ + c);
                *(float2*)(Cf + (size_t)r0     * D_ + c) = make_float2(x0 + r0v.x, x1 + r0v.y);
                *(float2*)(Cf + (size_t)(r0+8) * D_ + c) = make_float2(x2 + r1v.x, x3 + r1v.y);
            } else {
                uint32_t hp, lp;
                split2pack(x0, x1, hp, lp);
                *(uint32_t*)(Ch + (size_t)r0 * D_ + c) = hp;
                *(uint32_t*)(Cl + (size_t)r0 * D_ + c) = lp;
                split2pack(x2, x3, hp, lp);
                *(uint32_t*)(Ch + (size_t)(r0+8) * D_ + c) = hp;
                *(uint32_t*)(Cl + (size_t)(r0+8) * D_ + c) = lp;
            }
        }
    }
}

__global__ __launch_bounds__(256, 2)
void qkv_kernel(const __nv_bfloat16* __restrict__ xnh, const __nv_bfloat16* __restrict__ xnl,
                const __nv_bfloat16* __restrict__ wh,  const __nv_bfloat16* __restrict__ wl,
                __nv_bfloat16* __restrict__ qh, __nv_bfloat16* __restrict__ ql,
                __nv_bfloat16* __restrict__ kh, __nv_bfloat16* __restrict__ kl,
                __nv_bfloat16* __restrict__ vh, __nv_bfloat16* __restrict__ vl)
{
    const int z = blockIdx.z;
    __nv_bfloat16 *Ch, *Cl;
    if (z == 0)      { Ch = qh; Cl = ql; }
    else if (z == 1) { Ch = kh; Cl = kl; }
    else             { Ch = vh; Cl = vl; }
    const float scale = (z == 0) ? 0.125f : 1.0f;
    mma_gemm_body<1>(xnh, xnl, wh + (size_t)z*DD_, wl + (size_t)z*DD_,
                     nullptr, nullptr, Ch, Cl, scale);
}

__global__ __launch_bounds__(256, 2)
void out_kernel(const __nv_bfloat16* __restrict__ yh, const __nv_bfloat16* __restrict__ yl,
                const __nv_bfloat16* __restrict__ wh, const __nv_bfloat16* __restrict__ wl,
                const float* __restrict__ x, float* __restrict__ out)
{
    mma_gemm_body<0>(yh, yl, wh + (size_t)3*DD_, wl + (size_t)3*DD_,
                     out, x, nullptr, nullptr, 1.0f);
}

// ---------------- HMMA flash attention ---------------------------------------
// Grid (32, 16, 4), 128 threads = 4 warps; warp owns 16 Q rows.
// Q tile 64, K tile 64, split-bf16 3-pass for QK^T and PV.
// smem: QH 8K | QL 8K | stage{0,1}: KH 8K KL 8K VH 8K VL 8K  (swizzled 128B rows)
#define AQH 0
#define AQL 8192
#define AST 16384
#define ATTN_SMEM (16384 + 2*32768 + 1024)

__global__ __launch_bounds__(128)
void attn_tc(const __nv_bfloat16* __restrict__ qh, const __nv_bfloat16* __restrict__ ql,
             const __nv_bfloat16* __restrict__ kh, const __nv_bfloat16* __restrict__ kl,
             const __nv_bfloat16* __restrict__ vh, const __nv_bfloat16* __restrict__ vl,
             const float* __restrict__ rel,
             __nv_bfloat16* __restrict__ yh, __nv_bfloat16* __restrict__ yl)
{
    extern __shared__ char dynsm[];
    __shared__ float rels[MAXREL + 1];
    const uint32_t sb = (sm_u32(dynsm) + 1023u) & ~1023u;

    const int qb = 31 - (int)blockIdx.x;     // heavy blocks first
    const int h  = blockIdx.y;
    const int b  = blockIdx.z;
    const int tid = threadIdx.x;
    const int warp = tid >> 5, lane = tid & 31;
    const int nit = qb + 1;
    const int qrow0 = b*T_ + qb*64;
    const int hoff = h * DH_;

    auto LDQ = [&]() {
        #pragma unroll
        for (int t = 0; t < 4; t++) {
            const int idx = tid + t*128, r = idx >> 3, c = idx & 7;
            const uint32_t o = SMEM_SWZ(r*128 + c*16);
            const size_t gq = (size_t)(qrow0 + r)*D_ + hoff + c*8;
            CPA16(sb + AQH + o, qh + gq);
            CPA16(sb + AQL + o, ql + gq);
        }
    };
    auto LDKV = [&](int kb, int st) {
        const uint32_t s0 = sb + AST + st * 32768;
        const int krow0 = b*T_ + kb*64;
        #pragma unroll
        for (int t = 0; t < 4; t++) {
            const int idx = tid + t*128, r = idx >> 3, c = idx & 7;
            const uint32_t o = SMEM_SWZ(r*128 + c*16);
            const size_t gk = (size_t)(krow0 + r)*D_ + hoff + c*8;
            CPA16(s0 +         o, kh + gk);
            CPA16(s0 +  8192 + o, kl + gk);
            CPA16(s0 + 16384 + o, vh + gk);
            CPA16(s0 + 24576 + o, vl + gk);
        }
    };

    LDQ(); LDKV(0, 0); CPA_COMMIT();
    if (nit > 1) { LDKV(1, 1); CPA_COMMIT(); }
    for (int i = tid; i <= MAXREL; i += 128) rels[i] = rel[h*(MAXREL+1) + i];

    // fragment address components
    const int rA = warp*16 + (lane & 15);               // Q row
    const uint32_t xorA = (uint32_t)(rA & 7) * 16;
    const uint32_t qhb = sb + AQH + rA*128;
    const uint32_t qlb = sb + AQL + rA*128;
    const int chA = lane >> 4;                          // 0/1 (d chunk)

    const int rkoff = (lane & 7) + ((lane >> 4) & 1) * 8;   // K rows (non-trans B)
    const int ckK   = (lane >> 3) & 1;
    const int rvoff = (lane & 7) + ((lane >> 3) & 1) * 8;   // V rows (trans B)
    const int cvK   = (lane >> 4) & 1;
    const uint32_t xorL = (uint32_t)(lane & 7) * 16;

    float m0 = -1e30f, m1 = -1e30f, l0 = 0.f, l1 = 0.f;
    float o[8][4];
    #pragma unroll
    for (int dt = 0; dt < 8; dt++)
        #pragma unroll
        for (int e = 0; e < 4; e++) o[dt][e] = 0.f;

    const int rq0 = qb*64 + warp*16 + (lane >> 2);      // global i of row0 (row1 = +8)

    for (int it = 0; it < nit; it++) {
        if (it + 1 < nit) CPA_WAIT1(); else CPA_WAIT0();
        __syncthreads();
        const uint32_t s0 = sb + AST + (it & 1) * 32768;

        // -------- S = Q K^T (3-pass) --------
        float s[8][4];
        #pragma unroll
        for (int jt = 0; jt < 8; jt++)
            #pragma unroll
            for (int e = 0; e < 4; e++) s[jt][e] = 0.f;

        #pragma unroll
        for (int d8 = 0; d8 < 8; d8 += 2) {             // d0 = d8*8, k-step 16
            uint32_t aqhf[4], aqlf[4];
            const uint32_t ca = (uint32_t)((d8 + chA) * 16) ^ xorA;
            LDSM4(aqhf, qhb + ca);
            LDSM4(aqlf, qlb + ca);
            #pragma unroll
            for (int jp = 0; jp < 4; jp++) {
                const uint32_t ka = s0 + (uint32_t)(jp*16 + rkoff)*128
                                  + ((uint32_t)((d8 + ckK) * 16) ^ xorL);
                uint32_t bh4[4], bl4[4];
                LDSM4(bh4, ka);
                LDSM4(bl4, ka + 8192);
                mma16816(s[2*jp],   aqhf, bh4);
                mma16816(s[2*jp],   aqlf, bh4);
                mma16816(s[2*jp],   aqhf, bl4);
                mma16816(s[2*jp+1], aqhf, bh4 + 2);
                mma16816(s[2*jp+1], aqlf, bh4 + 2);
                mma16816(s[2*jp+1], aqhf, bl4 + 2);
            }
        }

        // -------- bias + causal mask --------
        const int jbase = it*64 + 2*(lane & 3);
        #pragma unroll
        for (int jt = 0; jt < 8; jt++) {
            #pragma unroll
            for (int e = 0; e < 2; e++) {
                const int jc = jbase + jt*8 + e;
                const int d0v = rq0 - jc;
                const int d1v = d0v + 8;
                s[jt][e]     = (d0v < 0) ? -1e30f : s[jt][e]     + rels[d0v > MAXREL ? MAXREL : d0v];
                s[jt][2 + e] = (d1v < 0) ? -1e30f : s[jt][2 + e] + rels[d1v > MAXREL ? MAXREL : d1v];
            }
        }

        // -------- online softmax --------
        float mx0 = -1e30f, mx1 = -1e30f;
        #pragma unroll
        for (int jt = 0; jt < 8; jt++) {
            mx0 = fmaxf(mx0, fmaxf(s[jt][0], s[jt][1]));
            mx1 = fmaxf(mx1, fmaxf(s[jt][2], s[jt][3]));
        }
        mx0 = fmaxf(mx0, __shfl_xor_sync(0xffffffffu, mx0, 1));
        mx0 = fmaxf(mx0, __shfl_xor_sync(0xffffffffu, mx0, 2));
        mx1 = fmaxf(mx1, __shfl_xor_sync(0xffffffffu, mx1, 1));
        mx1 = fmaxf(mx1, __shfl_xor_sync(0xffffffffu, mx1, 2));
        const float mn0 = fmaxf(m0, mx0), mn1 = fmaxf(m1, mx1);
        const float a0 = __expf(m0 - mn0), a1 = __expf(m1 - mn1);
        m0 = mn0; m1 = mn1;
        float rs0 = 0.f, rs1 = 0.f;
        #pragma unroll
        for (int jt = 0; jt < 8; jt++) {
            #pragma unroll
            for (int e = 0; e < 2; e++) {
                s[jt][e]     = __expf(s[jt][e]     - mn0);  rs0 += s[jt][e];
                s[jt][2 + e] = __expf(s[jt][2 + e] - mn1);  rs1 += s[jt][2 + e];
            }
        }
        rs0 += __shfl_xor_sync(0xffffffffu, rs0, 1);
        rs0 += __shfl_xor_sync(0xffffffffu, rs0, 2);
        rs1 += __shfl_xor_sync(0xffffffffu, rs1, 1);
        rs1 += __shfl_xor_sync(0xffffffffu, rs1, 2);
        l0 = l0 * a0 + rs0;
        l1 = l1 * a1 + rs1;
        #pragma unroll
        for (int dt = 0; dt < 8; dt++) {
            o[dt][0] *= a0; o[dt][1] *= a0;
            o[dt][2] *= a1; o[dt][3] *= a1;
        }

        // -------- O += P V (3-pass) --------
        #pragma unroll
        for (int jp = 0; jp < 4; jp++) {
            uint32_t ph[4], pl[4];
            split2pack(s[2*jp][0],   s[2*jp][1],   ph[0], pl[0]);
            split2pack(s[2*jp][2],   s[2*jp][3],   ph[1], pl[1]);
            split2pack(s[2*jp+1][0], s[2*jp+1][1], ph[2], pl[2]);
            split2pack(s[2*jp+1][2], s[2*jp+1][3], ph[3], pl[3]);
            #pragma unroll
            for (int dp = 0; dp < 4; dp++) {
                const uint32_t va = s0 + 16384 + (uint32_t)(jp*16 + rvoff)*128
                                  + ((uint32_t)((dp*2 + cvK) * 16) ^ xorL);
                uint32_t wh4[4], wl4[4];
                LDSM4T(wh4, va);
                LDSM4T(wl4, va + 8192);
                mma16816(o[2*dp],   ph, wh4);
                mma16816(o[2*dp],   pl, wh4);
                mma16816(o[2*dp],   ph, wl4);
                mma16816(o[2*dp+1], ph, wh4 + 2);
                mma16816(o[2*dp+1], pl, wh4 + 2);
                mma16816(o[2*dp+1], ph, wl4 + 2);
            }
        }

        __syncthreads();
        if (it + 2 < nit) { LDKV(it + 2, it & 1); CPA_COMMIT(); }
    }

    // -------- epilogue: normalize, split, store --------
    const float i0 = 1.0f / l0, i1 = 1.0f / l1;
    const int gr0 = qrow0 + warp*16 + (lane >> 2);
    const int colb = hoff + 2*(lane & 3);
    #pragma unroll
    for (int dt = 0; dt < 8; dt++) {
        const int col = colb + dt*8;
        uint32_t hp, lp;
        split2pack(o[dt][0] * i0, o[dt][1] * i0, hp, lp);
        *(uint32_t*)(yh + (size_t)gr0 * D_ + col) = hp;
        *(uint32_t*)(yl + (size_t)gr0 * D_ + col) = lp;
        split2pack(o[dt][2] * i1, o[dt][3] * i1, hp, lp);
        *(uint32_t*)(yh + (size_t)(gr0 + 8) * D_ + col) = hp;
        *(uint32_t*)(yl + (size_t)(gr0 + 8) * D_ + col) = lp;
    }
}

extern "C" void kernel_launch(void* const* d_in, const int* in_sizes, int n_in,
                              void* d_out, int out_size)
{
    const float* x     = (const float*)d_in[0];
    const float* Wq    = (const float*)d_in[1];
    const float* Wk    = (const float*)d_in[2];
    const float* Wv    = (const float*)d_in[3];
    const float* Wo    = (const float*)d_in[4];
    const float* rel   = (const float*)d_in[5];
    const float* gamma = (const float*)d_in[6];
    const float* beta  = (const float*)d_in[7];
    float* out = (float*)d_out;

    __nv_bfloat16 *p_xnh, *p_xnl, *p_wh, *p_wl, *p_yh, *p_yl;
    __nv_bfloat16 *p_qh, *p_ql, *p_kh, *p_kl, *p_vh, *p_vl;
    cudaGetSymbolAddress((void**)&p_xnh, g_xnh);
    cudaGetSymbolAddress((void**)&p_xnl, g_xnl);
    cudaGetSymbolAddress((void**)&p_wh,  g_wh);
    cudaGetSymbolAddress((void**)&p_wl,  g_wl);
    cudaGetSymbolAddress((void**)&p_yh,  g_yh);
    cudaGetSymbolAddress((void**)&p_yl,  g_yl);
    cudaGetSymbolAddress((void**)&p_qh,  g_qh);
    cudaGetSymbolAddress((void**)&p_ql,  g_ql);
    cudaGetSymbolAddress((void**)&p_kh,  g_kh);
    cudaGetSymbolAddress((void**)&p_kl,  g_kl);
    cudaGetSymbolAddress((void**)&p_vh,  g_vh);
    cudaGetSymbolAddress((void**)&p_vl,  g_vl);

    cudaFuncSetAttribute(qkv_kernel, cudaFuncAttributeMaxDynamicSharedMemorySize, GEMM_SMEM);
    cudaFuncSetAttribute(out_kernel, cudaFuncAttributeMaxDynamicSharedMemorySize, GEMM_SMEM);
    cudaFuncSetAttribute(attn_tc,    cudaFuncAttributeMaxDynamicSharedMemorySize, ATTN_SMEM);

    ln_kernel<<<M_, 256>>>(x, gamma, beta, p_xnh, p_xnl);
    wsplit_kernel<<<dim3(DD_/(256*4), 4), 256>>>(Wq, Wk, Wv, Wo, p_wh, p_wl);
    qkv_kernel<<<dim3(D_/128, M_/128, 3), 256, GEMM_SMEM>>>(p_xnh, p_xnl, p_wh, p_wl,
                                                            p_qh, p_ql, p_kh, p_kl, p_vh, p_vl);
    attn_tc<<<dim3(T_/64, H_, B_), 128, ATTN_SMEM>>>(p_qh, p_ql, p_kh, p_kl, p_vh, p_vl,
                                                     rel, p_yh, p_yl);
    out_kernel<<<dim3(D_/128, M_/128), 256, GEMM_SMEM>>>(p_yh, p_yl, p_wh, p_wl, x, out);
}